// round 4
// baseline (speedup 1.0000x reference)
#include <cuda_runtime.h>
#include <cstdint>

#define BLOCK 256
#define TILES 4                 // 256-row tiles per block
#define TILE_F4 (BLOCK * 4)     // float4 per tile (256 rows x 16 floats)

// ---------------------------------------------------------------------------
// BinaryTreeRNN: out[i] = tree_combine( x[i,0:16] @ W_leaf^T + b_leaf )
// Params folded into __constant__ (LDC/LDCU port). x staged via cp.async
// double-buffered pipeline (load tile i+1 while computing tile i).
// ---------------------------------------------------------------------------

struct __align__(16) CParams {
    float2 Wp[4][16];   // [pair p][k] = (W[2p][k], W[2p+1][k])
    float2 bp[4];       // (b_leaf[2p], b_leaf[2p+1])
    float4 node[7];     // (A, M, C, b): val = A*s + M*l*r + C*sin(s) + b
};

__constant__ CParams cP;
__device__ CParams gStage;

__global__ void setup_kernel(const float* __restrict__ W,
                             const float* __restrict__ bl,
                             const float* __restrict__ w0,
                             const float* __restrict__ w1,
                             const float* __restrict__ w2,
                             const float* __restrict__ b0,
                             const float* __restrict__ b1,
                             const float* __restrict__ b2,
                             const float* __restrict__ om0,
                             const float* __restrict__ om1,
                             const float* __restrict__ om2)
{
    int t = threadIdx.x;
    if (t < 64) {
        int p = t >> 4, k = t & 15;
        gStage.Wp[p][k] = make_float2(W[(2 * p) * 16 + k], W[(2 * p + 1) * 16 + k]);
    } else if (t < 68) {
        int p = t - 64;
        gStage.bp[p] = make_float2(bl[2 * p], bl[2 * p + 1]);
    } else if (t < 75) {
        int i = t - 68;   // 0-3: level2, 4-5: level1, 6: level0
        const float* om;
        float w, b;
        if (i < 4)      { om = om2 + 4 * i;       w = w2[i];     b = b2[i]; }
        else if (i < 6) { om = om1 + 4 * (i - 4); w = w1[i - 4]; b = b1[i - 4]; }
        else            { om = om0;               w = w0[0];     b = b0[0]; }
        float e0 = expf(om[0]);
        float e1 = expf(om[1]);
        float e2 = expf(om[2]);
        float e3 = expf(om[3]);
        float inv = w / (e0 + e1 + e2 + e3);   // fold w into softmax coeffs
        gStage.node[i] = make_float4((e0 + e3) * inv, e1 * inv, e2 * inv, b);
    }
}

// ---- packed fp32x2 + async-copy helpers (sm_103a) ---------------------------

__device__ __forceinline__ unsigned long long fma2(unsigned long long a,
                                                   unsigned long long b,
                                                   unsigned long long c)
{
    unsigned long long d;
    asm("fma.rn.f32x2 %0, %1, %2, %3;" : "=l"(d) : "l"(a), "l"(b), "l"(c));
    return d;
}

__device__ __forceinline__ unsigned long long dup2(float v)
{
    unsigned long long d;
    asm("mov.b64 %0, {%1, %1};" : "=l"(d) : "f"(v));
    return d;
}

__device__ __forceinline__ void unpack2(unsigned long long v, float& lo, float& hi)
{
    asm("mov.b64 {%0, %1}, %2;" : "=f"(lo), "=f"(hi) : "l"(v));
}

__device__ __forceinline__ void cp16(uint32_t smem_dst, const void* gsrc)
{
    asm volatile("cp.async.cg.shared.global [%0], [%1], 16;\n"
                 :: "r"(smem_dst), "l"(gsrc) : "memory");
}

__device__ __forceinline__ void cp_commit()
{
    asm volatile("cp.async.commit_group;\n" ::: "memory");
}

template <int N>
__device__ __forceinline__ void cp_wait()
{
    asm volatile("cp.async.wait_group %0;\n" :: "n"(N) : "memory");
}

// ---- main kernel -----------------------------------------------------------

__global__ void __launch_bounds__(BLOCK)
tree_rnn_kernel(const float4* __restrict__ x4, float* __restrict__ out, int n)
{
    __shared__ float4 tile[2][TILE_F4];
    const int t = threadIdx.x;
    const int block_row0 = blockIdx.x * (BLOCK * TILES);
    const int n4 = n * 4;

    // stage tile ti of this block into buffer buf (XOR-swizzled, cp.async)
    auto stage = [&](int ti, int buf) {
        int base4 = (block_row0 + ti * BLOCK) * 4;
#pragma unroll
        for (int j = 0; j < 4; j++) {
            int li = j * BLOCK + t;
            int g4 = base4 + li;
            int r = li >> 2, q = li & 3;
            uint32_t dst = (uint32_t)__cvta_generic_to_shared(
                &tile[buf][(r << 2) + (q ^ ((r >> 1) & 3))]);
            if (g4 < n4) cp16(dst, x4 + g4);
        }
        cp_commit();
    };

    stage(0, 0);

#pragma unroll
    for (int i = 0; i < TILES; i++) {
        if (i > 0) __syncthreads();        // all warps done computing tile i-1
        if (i + 1 < TILES) stage(i + 1, (i + 1) & 1);
        if (i + 1 < TILES) cp_wait<1>();   // tile i landed (i+1 may be in flight)
        else               cp_wait<0>();
        __syncthreads();                   // make everyone's cp.async visible

        const int row = block_row0 + i * BLOCK + t;
        if (row < n) {
            const float4* tb = tile[i & 1];
            const int swz = (t >> 1) & 3;
            float4 v0 = tb[(t << 2) + (0 ^ swz)];
            float4 v1 = tb[(t << 2) + (1 ^ swz)];
            float4 v2 = tb[(t << 2) + (2 ^ swz)];
            float4 v3 = tb[(t << 2) + (3 ^ swz)];

            unsigned long long xb[16];
            xb[0]  = dup2(v0.x); xb[1]  = dup2(v0.y); xb[2]  = dup2(v0.z); xb[3]  = dup2(v0.w);
            xb[4]  = dup2(v1.x); xb[5]  = dup2(v1.y); xb[6]  = dup2(v1.z); xb[7]  = dup2(v1.w);
            xb[8]  = dup2(v2.x); xb[9]  = dup2(v2.y); xb[10] = dup2(v2.z); xb[11] = dup2(v2.w);
            xb[12] = dup2(v3.x); xb[13] = dup2(v3.y); xb[14] = dup2(v3.z); xb[15] = dup2(v3.w);

            // leaf matvec: weights from the constant port (no L1TEX traffic)
            float h[8];
#pragma unroll
            for (int p = 0; p < 4; p++) {
                unsigned long long acc =
                    *reinterpret_cast<const unsigned long long*>(&cP.bp[p]);
#pragma unroll
                for (int k2 = 0; k2 < 8; k2++) {
                    ulonglong2 w =
                        *reinterpret_cast<const ulonglong2*>(&cP.Wp[p][2 * k2]);
                    acc = fma2(w.x, xb[2 * k2 + 0], acc);
                    acc = fma2(w.y, xb[2 * k2 + 1], acc);
                }
                unpack2(acc, h[2 * p + 0], h[2 * p + 1]);
            }

            // tree combine: val = A*s + M*(l*r) + C*sin(s) + b
            float g[4];
#pragma unroll
            for (int k = 0; k < 4; k++) {
                float4 np = cP.node[k];
                float l = h[2 * k], r = h[2 * k + 1];
                float s = l + r;
                g[k] = fmaf(np.x, s, fmaf(np.y, l * r, fmaf(np.z, __sinf(s), np.w)));
            }
            float u[2];
#pragma unroll
            for (int k = 0; k < 2; k++) {
                float4 np = cP.node[4 + k];
                float l = g[2 * k], r = g[2 * k + 1];
                float s = l + r;
                u[k] = fmaf(np.x, s, fmaf(np.y, l * r, fmaf(np.z, __sinf(s), np.w)));
            }
            {
                float4 np = cP.node[6];
                float l = u[0], r = u[1];
                float s = l + r;
                out[row] = fmaf(np.x, s, fmaf(np.y, l * r, fmaf(np.z, __sinf(s), np.w)));
            }
        }
    }
}

extern "C" void kernel_launch(void* const* d_in, const int* in_sizes, int n_in,
                              void* d_out, int out_size)
{
    const float* x      = (const float*)d_in[0];
    const float* W_leaf = (const float*)d_in[1];
    const float* b_leaf = (const float*)d_in[2];
    const float* w0     = (const float*)d_in[3];
    const float* w1     = (const float*)d_in[4];
    const float* w2     = (const float*)d_in[5];
    const float* b0     = (const float*)d_in[6];
    const float* b1     = (const float*)d_in[7];
    const float* b2     = (const float*)d_in[8];
    const float* om0    = (const float*)d_in[9];
    const float* om1    = (const float*)d_in[10];
    const float* om2    = (const float*)d_in[11];

    int n = in_sizes[0] / 16;

    setup_kernel<<<1, 128>>>(W_leaf, b_leaf, w0, w1, w2, b0, b1, b2,
                             om0, om1, om2);
    void* stage_ptr = nullptr;
    cudaGetSymbolAddress(&stage_ptr, gStage);
    cudaMemcpyToSymbolAsync(cP, stage_ptr, sizeof(CParams), 0,
                            cudaMemcpyDeviceToDevice);

    int rows_per_block = BLOCK * TILES;
    int blocks = (n + rows_per_block - 1) / rows_per_block;
    tree_rnn_kernel<<<blocks, BLOCK>>>(
        reinterpret_cast<const float4*>(x), (float*)d_out, n);
}

// round 5
// speedup vs baseline: 1.0156x; 1.0156x over previous
#include <cuda_runtime.h>
#include <cstdint>

// ---------------------------------------------------------------------------
// BinaryTreeRNN: out[i] = tree_combine( x[i,0:16] @ W_leaf^T + b_leaf )
// Params folded into __constant__ (LDC/LDCU port). x staged via WARP-LOCAL
// smem tiles (32 rows / 2KB per warp), software-pipelined: LDG of tile j+1
// overlaps compute of tile j. Only __syncwarp barriers -> warps drift freely,
// keeping DRAM requests in flight continuously.
// ---------------------------------------------------------------------------

struct __align__(16) CParams {
    float2 Wp[4][16];   // [pair p][k] = (W[2p][k], W[2p+1][k])
    float2 bp[4];       // (b_leaf[2p], b_leaf[2p+1])
    float4 node[7];     // (A, M, C, b): val = A*s + M*l*r + C*sin(s) + b
};

__constant__ CParams cP;
__device__ CParams gStage;

__global__ void setup_kernel(const float* __restrict__ W,
                             const float* __restrict__ bl,
                             const float* __restrict__ w0,
                             const float* __restrict__ w1,
                             const float* __restrict__ w2,
                             const float* __restrict__ b0,
                             const float* __restrict__ b1,
                             const float* __restrict__ b2,
                             const float* __restrict__ om0,
                             const float* __restrict__ om1,
                             const float* __restrict__ om2)
{
    int t = threadIdx.x;
    if (t < 64) {
        int p = t >> 4, k = t & 15;
        gStage.Wp[p][k] = make_float2(W[(2 * p) * 16 + k], W[(2 * p + 1) * 16 + k]);
    } else if (t < 68) {
        int p = t - 64;
        gStage.bp[p] = make_float2(bl[2 * p], bl[2 * p + 1]);
    } else if (t < 75) {
        int i = t - 68;   // 0-3: level2, 4-5: level1, 6: level0
        const float* om;
        float w, b;
        if (i < 4)      { om = om2 + 4 * i;       w = w2[i];     b = b2[i]; }
        else if (i < 6) { om = om1 + 4 * (i - 4); w = w1[i - 4]; b = b1[i - 4]; }
        else            { om = om0;               w = w0[0];     b = b0[0]; }
        float e0 = expf(om[0]);
        float e1 = expf(om[1]);
        float e2 = expf(om[2]);
        float e3 = expf(om[3]);
        float inv = w / (e0 + e1 + e2 + e3);   // fold w into softmax coeffs
        gStage.node[i] = make_float4((e0 + e3) * inv, e1 * inv, e2 * inv, b);
    }
}

// ---- packed fp32x2 helpers (sm_103a) --------------------------------------

__device__ __forceinline__ unsigned long long fma2(unsigned long long a,
                                                   unsigned long long b,
                                                   unsigned long long c)
{
    unsigned long long d;
    asm("fma.rn.f32x2 %0, %1, %2, %3;" : "=l"(d) : "l"(a), "l"(b), "l"(c));
    return d;
}

__device__ __forceinline__ unsigned long long dup2(float v)
{
    unsigned long long d;
    asm("mov.b64 %0, {%1, %1};" : "=l"(d) : "f"(v));
    return d;
}

__device__ __forceinline__ void unpack2(unsigned long long v, float& lo, float& hi)
{
    asm("mov.b64 {%0, %1}, %2;" : "=f"(lo), "=f"(hi) : "l"(v));
}

// ---- main kernel -----------------------------------------------------------

__global__ void __launch_bounds__(256)
tree_rnn_kernel(const float4* __restrict__ x4, float* __restrict__ out, int n)
{
    __shared__ float4 tile[8][128];      // 2KB slice per warp: 32 rows x 4 f4
    const int lane = threadIdx.x & 31;
    const int warp = threadIdx.x >> 5;
    float4* ts = tile[warp];

    const int nwarps = gridDim.x * 8;
    const int ntiles = (n + 31) >> 5;
    const int n4 = n * 4;

    int tl = blockIdx.x * 8 + warp;

    float4 v0, v1, v2, v3;
    if (tl < ntiles) {
        int b = tl * 128 + lane;
        v0 = (b      < n4) ? x4[b     ] : make_float4(0.f, 0.f, 0.f, 0.f);
        v1 = (b + 32 < n4) ? x4[b + 32] : make_float4(0.f, 0.f, 0.f, 0.f);
        v2 = (b + 64 < n4) ? x4[b + 64] : make_float4(0.f, 0.f, 0.f, 0.f);
        v3 = (b + 96 < n4) ? x4[b + 96] : make_float4(0.f, 0.f, 0.f, 0.f);
    }

    while (tl < ntiles) {
        // ---- STS current tile, XOR-swizzled (conflict-free) ----------------
        {
            int li, r, q;
            li = lane;      r = li >> 2; q = li & 3; ts[(r << 2) + (q ^ ((r >> 1) & 3))] = v0;
            li = 32 + lane; r = li >> 2; q = li & 3; ts[(r << 2) + (q ^ ((r >> 1) & 3))] = v1;
            li = 64 + lane; r = li >> 2; q = li & 3; ts[(r << 2) + (q ^ ((r >> 1) & 3))] = v2;
            li = 96 + lane; r = li >> 2; q = li & 3; ts[(r << 2) + (q ^ ((r >> 1) & 3))] = v3;
        }
        __syncwarp();

        // ---- gather own row (conflict-free via matching swizzle) -----------
        const int swz = (lane >> 1) & 3;
        float4 xv0 = ts[(lane << 2) + (0 ^ swz)];
        float4 xv1 = ts[(lane << 2) + (1 ^ swz)];
        float4 xv2 = ts[(lane << 2) + (2 ^ swz)];
        float4 xv3 = ts[(lane << 2) + (3 ^ swz)];
        __syncwarp();   // all lanes read slice before next iter's STS

        // ---- prefetch next tile (in flight during compute below) -----------
        const int row = tl * 32 + lane;
        const int nxt = tl + nwarps;
        if (nxt < ntiles) {
            int b = nxt * 128 + lane;
            v0 = (b      < n4) ? x4[b     ] : make_float4(0.f, 0.f, 0.f, 0.f);
            v1 = (b + 32 < n4) ? x4[b + 32] : make_float4(0.f, 0.f, 0.f, 0.f);
            v2 = (b + 64 < n4) ? x4[b + 64] : make_float4(0.f, 0.f, 0.f, 0.f);
            v3 = (b + 96 < n4) ? x4[b + 96] : make_float4(0.f, 0.f, 0.f, 0.f);
        }

        // ---- compute row ----------------------------------------------------
        if (row < n) {
            unsigned long long xb[16];
            xb[0]  = dup2(xv0.x); xb[1]  = dup2(xv0.y); xb[2]  = dup2(xv0.z); xb[3]  = dup2(xv0.w);
            xb[4]  = dup2(xv1.x); xb[5]  = dup2(xv1.y); xb[6]  = dup2(xv1.z); xb[7]  = dup2(xv1.w);
            xb[8]  = dup2(xv2.x); xb[9]  = dup2(xv2.y); xb[10] = dup2(xv2.z); xb[11] = dup2(xv2.w);
            xb[12] = dup2(xv3.x); xb[13] = dup2(xv3.y); xb[14] = dup2(xv3.z); xb[15] = dup2(xv3.w);

            // leaf matvec: weights from the constant port (no L1TEX traffic)
            float h[8];
#pragma unroll
            for (int p = 0; p < 4; p++) {
                unsigned long long acc =
                    *reinterpret_cast<const unsigned long long*>(&cP.bp[p]);
#pragma unroll
                for (int k2 = 0; k2 < 8; k2++) {
                    ulonglong2 w =
                        *reinterpret_cast<const ulonglong2*>(&cP.Wp[p][2 * k2]);
                    acc = fma2(w.x, xb[2 * k2 + 0], acc);
                    acc = fma2(w.y, xb[2 * k2 + 1], acc);
                }
                unpack2(acc, h[2 * p + 0], h[2 * p + 1]);
            }

            // tree combine: val = A*s + M*(l*r) + C*sin(s) + b
            float g[4];
#pragma unroll
            for (int k = 0; k < 4; k++) {
                float4 np = cP.node[k];
                float l = h[2 * k], r = h[2 * k + 1];
                float s = l + r;
                g[k] = fmaf(np.x, s, fmaf(np.y, l * r, fmaf(np.z, __sinf(s), np.w)));
            }
            float u[2];
#pragma unroll
            for (int k = 0; k < 2; k++) {
                float4 np = cP.node[4 + k];
                float l = g[2 * k], r = g[2 * k + 1];
                float s = l + r;
                u[k] = fmaf(np.x, s, fmaf(np.y, l * r, fmaf(np.z, __sinf(s), np.w)));
            }
            {
                float4 np = cP.node[6];
                float l = u[0], r = u[1];
                float s = l + r;
                out[row] = fmaf(np.x, s, fmaf(np.y, l * r, fmaf(np.z, __sinf(s), np.w)));
            }
        }

        tl = nxt;
    }
}

extern "C" void kernel_launch(void* const* d_in, const int* in_sizes, int n_in,
                              void* d_out, int out_size)
{
    const float* x      = (const float*)d_in[0];
    const float* W_leaf = (const float*)d_in[1];
    const float* b_leaf = (const float*)d_in[2];
    const float* w0     = (const float*)d_in[3];
    const float* w1     = (const float*)d_in[4];
    const float* w2     = (const float*)d_in[5];
    const float* b0     = (const float*)d_in[6];
    const float* b1     = (const float*)d_in[7];
    const float* b2     = (const float*)d_in[8];
    const float* om0    = (const float*)d_in[9];
    const float* om1    = (const float*)d_in[10];
    const float* om2    = (const float*)d_in[11];

    int n = in_sizes[0] / 16;

    setup_kernel<<<1, 128>>>(W_leaf, b_leaf, w0, w1, w2, b0, b1, b2,
                             om0, om1, om2);
    void* stage_ptr = nullptr;
    cudaGetSymbolAddress(&stage_ptr, gStage);
    cudaMemcpyToSymbolAsync(cP, stage_ptr, sizeof(CParams), 0,
                            cudaMemcpyDeviceToDevice);

    int ntiles = (n + 31) / 32;
    int blocks = 4 * 148;                       // persistent-style single wave
    int max_blocks = (ntiles + 7) / 8;
    if (blocks > max_blocks) blocks = max_blocks;
    if (blocks < 1) blocks = 1;

    tree_rnn_kernel<<<blocks, 256>>>(
        reinterpret_cast<const float4*>(x), (float*)d_out, n);
}